// round 9
// baseline (speedup 1.0000x reference)
#include <cuda_runtime.h>
#include <cuda_bf16.h>
#include <cstddef>

// DeformAttnOnnx — SMEM-tiled gather version.
//   value:              (16, 2500, 8, 32) fp32
//   sampling_locations: (16, 2000, 8, 1, 4, 2) fp32
//   attention_weights:  (16, 2000, 8, 1, 4)    fp32
//   out:                (16, 2000, 256) fp32
//
// CTA = (b, h, dh, qc): loads value[b, :, h, dh*16:+16] (2500 x 64B = 160KB)
// into SMEM once, then serves 500 queries' bilinear gathers from SMEM
// (29-cyc deterministic latency, no L2 round-trips in the inner loop).
// 4-lane group per query: lane j owns float4 d-slice [dh*16 + 4j, +4).

namespace {
constexpr int KK = 2500;       // 50*50
constexpr int H  = 8;
constexpr int NQ = 2000;
constexpr int FH = 50;
constexpr int FW = 50;
constexpr int THREADS = 1024;
constexpr int QC  = 4;                    // query chunks per (b,h,dh)
constexpr int QPC = NQ / QC;              // 500 queries per CTA
constexpr int GROUPS = THREADS / 4;       // 256 query-groups per pass
constexpr int BLOCKS = 16 * H * 2 * QC;   // 1024
constexpr int TILE_F4 = KK * 4;           // 10000 float4 = 160 KB
constexpr size_t SMEM_BYTES = (size_t)TILE_F4 * sizeof(float4);
}

__device__ __forceinline__ void fma4(float4& acc, float w, const float4& v) {
    acc.x = fmaf(w, v.x, acc.x);
    acc.y = fmaf(w, v.y, acc.y);
    acc.z = fmaf(w, v.z, acc.z);
    acc.w = fmaf(w, v.w, acc.w);
}

extern __shared__ float4 smem4[];   // [k*4 + j] = value[b, k, h, dh*16 + 4j .. +4)

__global__ __launch_bounds__(THREADS, 1) void deform_attn_smem_kernel(
    const float4* __restrict__ value,   // (b, k, h, d/4): k-stride 64 float4
    const float4* __restrict__ loc,     // (b, q, h): 2 float4
    const float4* __restrict__ aw,      // (b, q, h): 1 float4
    float4* __restrict__ out)           // (b, q, h*8 + dh*4 + j)
{
    const int cta = blockIdx.x;
    const int qc = cta & 3;
    const int dh = (cta >> 2) & 1;
    const int h  = (cta >> 3) & 7;
    const int b  = cta >> 6;
    const int tid = threadIdx.x;

    // ---- tile load: value[b, :, h, dh-half] -> smem (160 KB) ----
    const float4* src = value + (size_t)b * KK * 64 + h * 8 + dh * 4;
    for (int l = tid; l < TILE_F4; l += THREADS) {
        smem4[l] = __ldg(src + (size_t)(l >> 2) * 64 + (l & 3));
    }
    __syncthreads();

    const int j   = tid & 3;     // d-slice within the half
    const int gid = tid >> 2;    // query-group id

#pragma unroll
    for (int iter = 0; iter < 2; ++iter) {
        const int ql = iter * GROUPS + gid;
        if (ql >= QPC) break;
        const int q  = qc * QPC + ql;
        const int bq = b * NQ + q;
        const int lbase = bq * H + h;

        const float4 l0 = __ldg(&loc[lbase * 2 + 0]);
        const float4 l1 = __ldg(&loc[lbase * 2 + 1]);
        const float4 a  = __ldg(&aw[lbase]);

        const float lx[4] = {l0.x, l0.z, l1.x, l1.z};
        const float ly[4] = {l0.y, l0.w, l1.y, l1.w};
        const float av[4] = {a.x, a.y, a.z, a.w};

        float4 acc = make_float4(0.f, 0.f, 0.f, 0.f);

#pragma unroll
        for (int p = 0; p < 4; ++p) {
            const float x = lx[p] * (float)FW - 0.5f;
            const float y = ly[p] * (float)FH - 0.5f;
            const float xf = floorf(x);
            const float yf = floorf(y);
            const int ix = (int)xf;
            const int iy = (int)yf;
            const float wx1 = x - xf, wx0 = 1.0f - wx1;
            const float wy1 = y - yf, wy0 = 1.0f - wy1;
            const float aa = av[p];

            const float vx0 = ((unsigned)ix       < (unsigned)FW) ? 1.f : 0.f;
            const float vx1 = ((unsigned)(ix + 1) < (unsigned)FW) ? 1.f : 0.f;
            const float vy0 = ((unsigned)iy       < (unsigned)FH) ? 1.f : 0.f;
            const float vy1 = ((unsigned)(iy + 1) < (unsigned)FH) ? 1.f : 0.f;

            const int ix0 = min(max(ix,     0), FW - 1);
            const int ix1 = min(max(ix + 1, 0), FW - 1);
            const int iy0 = min(max(iy,     0), FH - 1);
            const int iy1 = min(max(iy + 1, 0), FH - 1);

            const int r0 = iy0 * FW;
            const int r1 = iy1 * FW;

            const float w00 = aa * wx0 * wy0 * (vx0 * vy0);
            const float w10 = aa * wx1 * wy0 * (vx1 * vy0);
            const float w01 = aa * wx0 * wy1 * (vx0 * vy1);
            const float w11 = aa * wx1 * wy1 * (vx1 * vy1);

            const float4 v00 = smem4[(r0 + ix0) * 4 + j];
            const float4 v10 = smem4[(r0 + ix1) * 4 + j];
            const float4 v01 = smem4[(r1 + ix0) * 4 + j];
            const float4 v11 = smem4[(r1 + ix1) * 4 + j];

            fma4(acc, w00, v00);
            fma4(acc, w10, v10);
            fma4(acc, w01, v01);
            fma4(acc, w11, v11);
        }

        // out float4 index: bq*64 + h*8 + dh*4 + j  (64B contiguous per group)
        __stcs(&out[(size_t)bq * 64 + h * 8 + dh * 4 + j], acc);
    }
}

extern "C" void kernel_launch(void* const* d_in, const int* in_sizes, int n_in,
                              void* d_out, int out_size) {
    (void)in_sizes; (void)n_in; (void)out_size;
    const float4* value = (const float4*)d_in[0];
    const float4* loc   = (const float4*)d_in[2];
    const float4* aw    = (const float4*)d_in[3];
    float4* out         = (float4*)d_out;

    cudaFuncSetAttribute(deform_attn_smem_kernel,
                         cudaFuncAttributeMaxDynamicSharedMemorySize,
                         (int)SMEM_BYTES);

    deform_attn_smem_kernel<<<BLOCKS, THREADS, SMEM_BYTES>>>(value, loc, aw, out);
}

// round 11
// speedup vs baseline: 1.7585x; 1.7585x over previous
#include <cuda_runtime.h>
#include <cuda_bf16.h>
#include <cstddef>

// DeformAttnOnnx — direct gather with per-SM (b,h) locality.
//   value:              (16, 2500, 8, 32) fp32
//   sampling_locations: (16, 2000, 8, 1, 4, 2) fp32
//   attention_weights:  (16, 2000, 8, 1, 4)    fp32
//   out:                (16, 2000, 256) fp32
//
// grid = 128 CTAs, one per (b,h). Each CTA serves all 2000 queries of its
// (b,h), so the 320KB value slice it gathers from stays (mostly) resident in
// that SM's 228KB L1 — the ~12.8x reuse per value line is concentrated on one
// SM instead of being spread chip-wide through L2.
// 8-lane group per query: lane sub owns float4 d-slice [4*sub,+4); every
// corner fetch is one fully-utilized 128B line (1 L1 wavefront).
// loc/aw go through __ldcg (L2-only) so they never evict value from L1.

namespace {
constexpr int KK = 2500;       // 50*50
constexpr int H  = 8;
constexpr int NQ = 2000;
constexpr int FH = 50;
constexpr int FW = 50;
constexpr int THREADS = 1024;
constexpr int GROUPS  = THREADS / 8;   // 128 query-groups per CTA pass
constexpr int BLOCKS  = 16 * H;        // 128: one CTA per (b,h)
}

__device__ __forceinline__ void fma4(float4& acc, float w, const float4& v) {
    acc.x = fmaf(w, v.x, acc.x);
    acc.y = fmaf(w, v.y, acc.y);
    acc.z = fmaf(w, v.z, acc.z);
    acc.w = fmaf(w, v.w, acc.w);
}

__device__ __forceinline__ float4 ldcg4(const float4* p) {
    float4 v;
    asm volatile("ld.global.cg.v4.f32 {%0,%1,%2,%3}, [%4];"
                 : "=f"(v.x), "=f"(v.y), "=f"(v.z), "=f"(v.w)
                 : "l"(p));
    return v;
}

__global__ __launch_bounds__(THREADS, 1) void deform_attn_kernel(
    const float4* __restrict__ value,   // (b, k, h, d/4): k-stride 64 float4
    const float4* __restrict__ loc,     // (b, q, h): 2 float4
    const float4* __restrict__ aw,      // (b, q, h): 1 float4
    float4* __restrict__ out)           // (b, q, h*8 + sub)
{
    const int h = blockIdx.x & 7;
    const int b = blockIdx.x >> 3;
    const int tid = threadIdx.x;
    const int sub = tid & 7;             // float4 d-slice
    const int gid = tid >> 3;            // query-group 0..127

    // value base for (b, h, sub); k stride = 64 float4
    const float4* vbase = value + ((size_t)b * KK * H + h) * 8 + sub;

    for (int q = gid; q < NQ; q += GROUPS) {
        const int bq = b * NQ + q;
        const int lbase = bq * H + h;

        // L2-only loads: keep L1 dedicated to value lines
        const float4 l0 = ldcg4(&loc[lbase * 2 + 0]);
        const float4 l1 = ldcg4(&loc[lbase * 2 + 1]);
        const float4 a  = ldcg4(&aw[lbase]);

        const float lx[4] = {l0.x, l0.z, l1.x, l1.z};
        const float ly[4] = {l0.y, l0.w, l1.y, l1.w};
        const float av[4] = {a.x, a.y, a.z, a.w};

        float4 acc = make_float4(0.f, 0.f, 0.f, 0.f);

#pragma unroll
        for (int p = 0; p < 4; ++p) {
            const float x = lx[p] * (float)FW - 0.5f;
            const float y = ly[p] * (float)FH - 0.5f;
            const float xf = floorf(x);
            const float yf = floorf(y);
            const int ix = (int)xf;
            const int iy = (int)yf;
            const float wx1 = x - xf, wx0 = 1.0f - wx1;
            const float wy1 = y - yf, wy0 = 1.0f - wy1;
            const float aa = av[p];

            // zeros padding folded into weights; loads made safe by clamping
            const float vx0 = ((unsigned)ix       < (unsigned)FW) ? 1.f : 0.f;
            const float vx1 = ((unsigned)(ix + 1) < (unsigned)FW) ? 1.f : 0.f;
            const float vy0 = ((unsigned)iy       < (unsigned)FH) ? 1.f : 0.f;
            const float vy1 = ((unsigned)(iy + 1) < (unsigned)FH) ? 1.f : 0.f;

            const int ix0 = min(max(ix,     0), FW - 1);
            const int ix1 = min(max(ix + 1, 0), FW - 1);
            const int iy0 = min(max(iy,     0), FH - 1);
            const int iy1 = min(max(iy + 1, 0), FH - 1);

            const int r0 = iy0 * FW;
            const int r1 = iy1 * FW;

            const float w00 = aa * wx0 * wy0 * (vx0 * vy0);
            const float w10 = aa * wx1 * wy0 * (vx1 * vy0);
            const float w01 = aa * wx0 * wy1 * (vx0 * vy1);
            const float w11 = aa * wx1 * wy1 * (vx1 * vy1);

            const float4 v00 = __ldg(vbase + (size_t)(r0 + ix0) * 64);
            const float4 v10 = __ldg(vbase + (size_t)(r0 + ix1) * 64);
            const float4 v01 = __ldg(vbase + (size_t)(r1 + ix0) * 64);
            const float4 v11 = __ldg(vbase + (size_t)(r1 + ix1) * 64);

            fma4(acc, w00, v00);
            fma4(acc, w10, v10);
            fma4(acc, w01, v01);
            fma4(acc, w11, v11);
        }

        // streaming store; 64B contiguous per 8-lane group
        __stcs(&out[(size_t)bq * 64 + h * 8 + sub], acc);
    }
}

extern "C" void kernel_launch(void* const* d_in, const int* in_sizes, int n_in,
                              void* d_out, int out_size) {
    (void)in_sizes; (void)n_in; (void)out_size;
    const float4* value = (const float4*)d_in[0];
    const float4* loc   = (const float4*)d_in[2];
    const float4* aw    = (const float4*)d_in[3];
    float4* out         = (float4*)d_out;

    deform_attn_kernel<<<BLOCKS, THREADS>>>(value, loc, aw, out);
}

// round 13
// speedup vs baseline: 1.7615x; 1.0017x over previous
#include <cuda_runtime.h>
#include <cuda_bf16.h>
#include <cstddef>

// DeformAttnOnnx — per-(b,h) locality + software-pipelined parameter loads.
//   value:              (16, 2500, 8, 32) fp32
//   sampling_locations: (16, 2000, 8, 1, 4, 2) fp32
//   attention_weights:  (16, 2000, 8, 1, 4)    fp32
//   out:                (16, 2000, 256) fp32
//
// grid = 128 CTAs, one per (b,h): the 320KB value slice concentrates its
// ~12.8x reuse in one SM's L1 (round-11 ncu: L2 dropped 56%->20%).
// This round: loc/aw loads use the schedulable __ldcg intrinsic and are
// explicitly prefetched one iteration ahead, so their L2 round-trip overlaps
// the current query's 16 gather loads instead of serializing ahead of them.

namespace {
constexpr int KK = 2500;       // 50*50
constexpr int H  = 8;
constexpr int NQ = 2000;
constexpr int FH = 50;
constexpr int FW = 50;
constexpr int THREADS = 1024;
constexpr int GROUPS  = THREADS / 8;   // 128 query-groups per CTA pass
constexpr int BLOCKS  = 16 * H;        // 128: one CTA per (b,h)
}

__device__ __forceinline__ void fma4(float4& acc, float w, const float4& v) {
    acc.x = fmaf(w, v.x, acc.x);
    acc.y = fmaf(w, v.y, acc.y);
    acc.z = fmaf(w, v.z, acc.z);
    acc.w = fmaf(w, v.w, acc.w);
}

__global__ __launch_bounds__(THREADS, 1) void deform_attn_kernel(
    const float4* __restrict__ value,   // (b, k, h, d/4): k-stride 64 float4
    const float4* __restrict__ loc,     // (b, q, h): 2 float4
    const float4* __restrict__ aw,      // (b, q, h): 1 float4
    float4* __restrict__ out)           // (b, q, h*8 + sub)
{
    const int h = blockIdx.x & 7;
    const int b = blockIdx.x >> 3;
    const int tid = threadIdx.x;
    const int sub = tid & 7;             // float4 d-slice
    const int gid = tid >> 3;            // query-group 0..127

    // value base for (b, h, sub); k stride = 64 float4
    const float4* vbase = value + ((size_t)b * KK * H + h) * 8 + sub;

    // ---- prologue: prefetch first iteration's parameters (L2-only) ----
    int lbase = (b * NQ + gid) * H + h;
    float4 nl0 = __ldcg(&loc[lbase * 2 + 0]);
    float4 nl1 = __ldcg(&loc[lbase * 2 + 1]);
    float4 na  = __ldcg(&aw[lbase]);

    for (int q = gid; q < NQ; q += GROUPS) {
        // consume current parameters
        const float lx[4] = {nl0.x, nl0.z, nl1.x, nl1.z};
        const float ly[4] = {nl0.y, nl0.w, nl1.y, nl1.w};
        const float av[4] = {na.x, na.y, na.z, na.w};

        // prefetch next iteration's parameters — overlaps the gathers below
        const int nq = q + GROUPS;
        if (nq < NQ) {
            const int nlb = (b * NQ + nq) * H + h;
            nl0 = __ldcg(&loc[nlb * 2 + 0]);
            nl1 = __ldcg(&loc[nlb * 2 + 1]);
            na  = __ldcg(&aw[nlb]);
        }

        float4 acc = make_float4(0.f, 0.f, 0.f, 0.f);

#pragma unroll
        for (int p = 0; p < 4; ++p) {
            const float x = lx[p] * (float)FW - 0.5f;
            const float y = ly[p] * (float)FH - 0.5f;
            const float xf = floorf(x);
            const float yf = floorf(y);
            const int ix = (int)xf;
            const int iy = (int)yf;
            const float wx1 = x - xf, wx0 = 1.0f - wx1;
            const float wy1 = y - yf, wy0 = 1.0f - wy1;
            const float aa = av[p];

            // zeros padding folded into weights; loads made safe by clamping
            const float vx0 = ((unsigned)ix       < (unsigned)FW) ? 1.f : 0.f;
            const float vx1 = ((unsigned)(ix + 1) < (unsigned)FW) ? 1.f : 0.f;
            const float vy0 = ((unsigned)iy       < (unsigned)FH) ? 1.f : 0.f;
            const float vy1 = ((unsigned)(iy + 1) < (unsigned)FH) ? 1.f : 0.f;

            const int ix0 = min(max(ix,     0), FW - 1);
            const int ix1 = min(max(ix + 1, 0), FW - 1);
            const int iy0 = min(max(iy,     0), FH - 1);
            const int iy1 = min(max(iy + 1, 0), FH - 1);

            const int r0 = iy0 * FW;
            const int r1 = iy1 * FW;

            const float w00 = aa * wx0 * wy0 * (vx0 * vy0);
            const float w10 = aa * wx1 * wy0 * (vx1 * vy0);
            const float w01 = aa * wx0 * wy1 * (vx0 * vy1);
            const float w11 = aa * wx1 * wy1 * (vx1 * vy1);

            const float4 v00 = __ldg(vbase + (size_t)(r0 + ix0) * 64);
            const float4 v10 = __ldg(vbase + (size_t)(r0 + ix1) * 64);
            const float4 v01 = __ldg(vbase + (size_t)(r1 + ix0) * 64);
            const float4 v11 = __ldg(vbase + (size_t)(r1 + ix1) * 64);

            fma4(acc, w00, v00);
            fma4(acc, w10, v10);
            fma4(acc, w01, v01);
            fma4(acc, w11, v11);
        }

        // streaming store; 64B contiguous per 8-lane group
        __stcs(&out[(size_t)(b * NQ + q) * 64 + h * 8 + sub], acc);
    }
}

extern "C" void kernel_launch(void* const* d_in, const int* in_sizes, int n_in,
                              void* d_out, int out_size) {
    (void)in_sizes; (void)n_in; (void)out_size;
    const float4* value = (const float4*)d_in[0];
    const float4* loc   = (const float4*)d_in[2];
    const float4* aw    = (const float4*)d_in[3];
    float4* out         = (float4*)d_out;

    deform_attn_kernel<<<BLOCKS, THREADS>>>(value, loc, aw, out);
}

// round 14
// speedup vs baseline: 1.8732x; 1.0634x over previous
#include <cuda_runtime.h>
#include <cuda_bf16.h>
#include <cstddef>

// DeformAttnOnnx — chip-wide 8-lane gather, instruction-slimmed.
//   value:              (16, 2500, 8, 32) fp32
//   sampling_locations: (16, 2000, 8, 1, 4, 2) fp32  (values in [0,1))
//   attention_weights:  (16, 2000, 8, 1, 4)    fp32
//   out:                (16, 2000, 256) fp32
//
// One 8-lane group per (b,q,h); lane sub owns float4 d-slice [4*sub,+4) so
// every corner fetch is one fully-utilized 128B line (1 L1 wavefront).
// Issue-slot economy (round-13 analysis: issue slots, not memory BW, bind):
//  - loc in [0,1) => ix in [-1,49]: single-sided clamps are provably safe.
//  - validity folded into edge weights via SEL; aa pre-multiplied into wy.
// loc/aw bypass L1 (__ldcg); output streams past L2 (__stcs).

namespace {
constexpr int KK = 2500;      // 50*50
constexpr int H  = 8;
constexpr int NQ = 2000;
constexpr int FH = 50;
constexpr int FW = 50;
constexpr int THREADS = 256;
constexpr int BLOCKS = 16 * NQ * H * 8 / THREADS;  // 8000
}

__device__ __forceinline__ void fma4(float4& acc, float w, const float4& v) {
    acc.x = fmaf(w, v.x, acc.x);
    acc.y = fmaf(w, v.y, acc.y);
    acc.z = fmaf(w, v.z, acc.z);
    acc.w = fmaf(w, v.w, acc.w);
}

__global__ __launch_bounds__(THREADS) void deform_attn_kernel(
    const float4* __restrict__ value,   // (b, k, h, d/4): k-stride 64 float4
    const float4* __restrict__ loc,     // (b, q, h): 2 float4
    const float4* __restrict__ aw,      // (b, q, h): 1 float4
    float4* __restrict__ out)           // (b, q, h*8 + sub)
{
    const int tid = blockIdx.x * THREADS + threadIdx.x;
    const int sub = tid & 7;            // float4 d-slice
    const int g   = tid >> 3;           // group = (b*NQ + q)*H + h, h fastest
    const int h   = g & 7;
    const int bq  = g >> 3;
    const int b   = bq / NQ;

    const int lbase = bq * H + h;
    const float4 l0 = __ldcg(&loc[lbase * 2 + 0]);
    const float4 l1 = __ldcg(&loc[lbase * 2 + 1]);
    const float4 a  = __ldcg(&aw[lbase]);

    const float lx[4] = {l0.x, l0.z, l1.x, l1.z};
    const float ly[4] = {l0.y, l0.w, l1.y, l1.w};
    const float av[4] = {a.x, a.y, a.z, a.w};

    // value base for (b, h, sub); k stride = 64 float4
    const float4* vbase = value + ((size_t)b * KK * H + h) * 8 + sub;

    float4 acc = make_float4(0.f, 0.f, 0.f, 0.f);

#pragma unroll
    for (int p = 0; p < 4; ++p) {
        const float x = fmaf(lx[p], (float)FW, -0.5f);
        const float y = fmaf(ly[p], (float)FH, -0.5f);
        const float xf = floorf(x);
        const float yf = floorf(y);
        const int ix = (int)xf;          // in [-1, 49] given loc in [0,1)
        const int iy = (int)yf;
        const float wx1 = x - xf, wx0 = 1.0f - wx1;
        const float wy1 = y - yf, wy0 = 1.0f - wy1;
        const float aa = av[p];

        // single-sided clamps (provably in-bounds for loc in [0,1))
        const int ix0 = max(ix, 0);
        const int ix1 = min(ix + 1, FW - 1);
        const int iy0 = max(iy, 0);
        const int iy1 = min(iy + 1, FH - 1);

        // zeros padding folded directly into the edge weights (SEL each)
        const float wx0z = (ix >= 0)      ? wx0 : 0.f;
        const float wx1z = (ix < FW - 1)  ? wx1 : 0.f;
        const float wy0z = ((iy >= 0)     ? wy0 : 0.f) * aa;
        const float wy1z = ((iy < FH - 1) ? wy1 : 0.f) * aa;

        const int r0 = iy0 * FW;
        const int r1 = iy1 * FW;

        const float4 v00 = __ldg(vbase + (size_t)(r0 + ix0) * 64);
        const float4 v10 = __ldg(vbase + (size_t)(r0 + ix1) * 64);
        const float4 v01 = __ldg(vbase + (size_t)(r1 + ix0) * 64);
        const float4 v11 = __ldg(vbase + (size_t)(r1 + ix1) * 64);

        fma4(acc, wx0z * wy0z, v00);
        fma4(acc, wx1z * wy0z, v10);
        fma4(acc, wx0z * wy1z, v01);
        fma4(acc, wx1z * wy1z, v11);
    }

    // streaming store: out is written once; 512B contiguous per warp
    __stcs(&out[(size_t)bq * 64 + h * 8 + sub], acc);
}

extern "C" void kernel_launch(void* const* d_in, const int* in_sizes, int n_in,
                              void* d_out, int out_size) {
    (void)in_sizes; (void)n_in; (void)out_size;
    const float4* value = (const float4*)d_in[0];
    const float4* loc   = (const float4*)d_in[2];
    const float4* aw    = (const float4*)d_in[3];
    float4* out         = (float4*)d_out;

    deform_attn_kernel<<<BLOCKS, THREADS>>>(value, loc, aw, out);
}